// round 4
// baseline (speedup 1.0000x reference)
#include <cuda_runtime.h>
#include <cuda_bf16.h>

#define SQ   1024
#define DD   64
#define HH   8
#define BM   128
#define BN   64
#define NCLIP3 579
#define MASKED_S (-50.0f)

// ---- packed f32x2 helpers (Blackwell FFMA2 path) ----
__device__ __forceinline__ unsigned long long pk2(float x, float y) {
    unsigned long long u;
    asm("mov.b64 %0, {%1,%2};" : "=l"(u) : "f"(x), "f"(y));
    return u;
}
__device__ __forceinline__ float2 upk2(unsigned long long u) {
    float2 r;
    asm("mov.b64 {%0,%1}, %2;" : "=f"(r.x), "=f"(r.y) : "l"(u));
    return r;
}
__device__ __forceinline__ unsigned long long ffma2(unsigned long long a,
                                                    unsigned long long b,
                                                    unsigned long long c) {
    unsigned long long d;
    asm("fma.rn.f32x2 %0, %1, %2, %3;" : "=l"(d) : "l"(a), "l"(b), "l"(c));
    return d;
}

// Mask per category.
// CAT 0 (t2i): eye ^ ((!pad && causal) || full)
// CAT 1 (lm):  causal
// CAT 2 (mmu): causal || kv <= 579
template <int CAT>
__device__ __forceinline__ bool mask_fn(int r, int kv, int pad_end, int fs, int fe) {
    if (CAT == 1) return r >= kv;
    if (CAT == 2) return (r >= kv) || (kv <= NCLIP3);
    bool pad    = kv < pad_end;
    bool causal = (!pad) && (r >= kv);
    bool full   = (kv >= fs) && (kv < fe);
    return ((r == kv) ? 1 : 0) ^ ((causal || full) ? 1 : 0);
}

template <int CAT>
__device__ __forceinline__ void tile_compute(
    const float4* __restrict__ Ks, const float4* __restrict__ Vs,
    const int* __restrict__ pads,
    unsigned long long* __restrict__ qreg,  // 32 pairs
    unsigned long long* __restrict__ O,     // 32 pairs
    float& l, int r, int kv0, int fs, int fe)
{
#pragma unroll 2
    for (int j = 0; j < BN; ++j) {
        int kv = kv0 + j;
        const ulonglong2* kj = reinterpret_cast<const ulonglong2*>(Ks + j * 16);
        unsigned long long a0 = 0ull, a1 = 0ull, a2 = 0ull, a3 = 0ull;
#pragma unroll
        for (int i = 0; i < 16; i += 2) {
            ulonglong2 k0 = kj[i];
            ulonglong2 k1 = kj[i + 1];
            a0 = ffma2(qreg[2 * i + 0], k0.x, a0);
            a1 = ffma2(qreg[2 * i + 1], k0.y, a1);
            a2 = ffma2(qreg[2 * i + 2], k1.x, a2);
            a3 = ffma2(qreg[2 * i + 3], k1.y, a3);
        }
        float2 f0 = upk2(a0), f1 = upk2(a1), f2 = upk2(a2), f3 = upk2(a3);
        float s = ((f0.x + f0.y) + (f1.x + f1.y)) + ((f2.x + f2.y) + (f3.x + f3.y));

        bool msk = mask_fn<CAT>(r, kv, pads[j], fs, fe);
        s = msk ? s : MASKED_S;

        float p = __expf(s);
        l += p;
        unsigned long long pp = pk2(p, p);

        const ulonglong2* vj = reinterpret_cast<const ulonglong2*>(Vs + j * 16);
#pragma unroll
        for (int i = 0; i < 16; ++i) {
            ulonglong2 vv = vj[i];
            O[2 * i + 0] = ffma2(pp, vv.x, O[2 * i + 0]);
            O[2 * i + 1] = ffma2(pp, vv.y, O[2 * i + 1]);
        }
    }
}

__global__ void __launch_bounds__(BM)
omni_attn_kernel(const float* __restrict__ q,
                 const float* __restrict__ k,
                 const float* __restrict__ v,
                 const int* __restrict__ pad_ends,
                 const int* __restrict__ full_starts,
                 const int* __restrict__ full_ends,
                 const int* __restrict__ p_bt2i,
                 const int* __restrict__ p_blm,
                 float* __restrict__ out)
{
    __shared__ float4 Ks[BN * 16];  // [64 rows][64 floats]
    __shared__ float4 Vs[BN * 16];
    __shared__ int    pads[BN];

    const int head = blockIdx.y;              // b*H + h, 0..95
    const int b    = head / HH;
    const int q0   = blockIdx.x * BM;
    const int r    = q0 + threadIdx.x;        // this thread's query row

    const int bt2i = p_bt2i[0];
    const int blm  = p_blm[0];
    const int cat  = (b < bt2i) ? 0 : ((b < bt2i + blm) ? 1 : 2);

    // --- load q row into registers, pre-scaled by 1/sqrt(D) ---
    const float scale = 0.125f;
    unsigned long long qreg[32];
    {
        const float4* qp = reinterpret_cast<const float4*>(
            q + ((size_t)head * SQ + r) * DD);
#pragma unroll
        for (int i = 0; i < 16; ++i) {
            float4 t = qp[i];
            qreg[2 * i + 0] = pk2(t.x * scale, t.y * scale);
            qreg[2 * i + 1] = pk2(t.z * scale, t.w * scale);
        }
    }

    unsigned long long O[32];
#pragma unroll
    for (int i = 0; i < 32; ++i) O[i] = 0ull;   // (0.0f, 0.0f)
    float l = 0.0f;

    int fs = 0, fe = 0;
    if (cat == 0) { fs = full_starts[r]; fe = full_ends[r]; }

    // number of kv tiles to visit
    int nt;
    if (cat == 0)      nt = SQ / BN;
    else if (cat == 1) nt = (q0 + BM) / BN;                      // causal: kv <= q_max
    else {
        int ntc = (q0 + BM) / BN;
        int ntm = NCLIP3 / BN + 1;                               // always-on strip
        nt = (ntc > ntm) ? ntc : ntm;
        if (nt > SQ / BN) nt = SQ / BN;
    }

    const float* kbase  = k + (size_t)head * SQ * DD;
    const float* vbase  = v + (size_t)head * SQ * DD;
    const int*   padrow = pad_ends + b * SQ;

    for (int t = 0; t < nt; ++t) {
        const int kv0 = t * BN;
        __syncthreads();
        // stage K/V tile (64x64 f32 each), fully coalesced
        const float4* kg = reinterpret_cast<const float4*>(kbase + (size_t)kv0 * DD);
        const float4* vg = reinterpret_cast<const float4*>(vbase + (size_t)kv0 * DD);
#pragma unroll
        for (int i = 0; i < 8; ++i) {
            int idx = threadIdx.x + i * BM;   // 0..1023
            Ks[idx] = kg[idx];
            Vs[idx] = vg[idx];
        }
        if (threadIdx.x < BN) pads[threadIdx.x] = padrow[kv0 + threadIdx.x];
        __syncthreads();

        if (cat == 0)      tile_compute<0>(Ks, Vs, pads, qreg, O, l, r, kv0, fs, fe);
        else if (cat == 1) tile_compute<1>(Ks, Vs, pads, qreg, O, l, r, kv0, fs, fe);
        else               tile_compute<2>(Ks, Vs, pads, qreg, O, l, r, kv0, fs, fe);
    }

    // --- epilogue: normalize and store ---
    const float inv = 1.0f / l;
    float4* op = reinterpret_cast<float4*>(out + ((size_t)head * SQ + r) * DD);
#pragma unroll
    for (int i = 0; i < 16; ++i) {
        float2 x = upk2(O[2 * i + 0]);
        float2 y = upk2(O[2 * i + 1]);
        float4 o;
        o.x = x.x * inv; o.y = x.y * inv;
        o.z = y.x * inv; o.w = y.y * inv;
        op[i] = o;
    }
}

extern "C" void kernel_launch(void* const* d_in, const int* in_sizes, int n_in,
                              void* d_out, int out_size) {
    const float* q  = (const float*)d_in[0];
    const float* k  = (const float*)d_in[1];
    const float* v  = (const float*)d_in[2];
    const int* pad_ends    = (const int*)d_in[3];
    const int* full_starts = (const int*)d_in[4];
    const int* full_ends   = (const int*)d_in[5];
    const int* bt2i        = (const int*)d_in[6];
    const int* blm         = (const int*)d_in[7];
    float* out = (float*)d_out;

    const int BH = 12 * HH;                   // 96 heads
    dim3 grid(SQ / BM, BH);
    dim3 block(BM);
    omni_attn_kernel<<<grid, block>>>(q, k, v, pad_ends, full_starts, full_ends,
                                      bt2i, blm, out);
}

// round 5
// speedup vs baseline: 1.3947x; 1.3947x over previous
#include <cuda_runtime.h>
#include <cuda_bf16.h>

#define SQ   1024
#define DD   64
#define HH   8
#define BM   128
#define BN   64
#define QPAD 68
#define NCLIP3 579
#define MASKED_S (-50.0f)

// ---- packed f32x2 helpers ----
__device__ __forceinline__ unsigned long long pk2b(float x) {   // broadcast (x,x)
    unsigned long long u;
    asm("mov.b64 %0, {%1,%1};" : "=l"(u) : "f"(x));
    return u;
}
__device__ __forceinline__ float2 upk2(unsigned long long u) {
    float2 r;
    asm("mov.b64 {%0,%1}, %2;" : "=f"(r.x), "=f"(r.y) : "l"(u));
    return r;
}
__device__ __forceinline__ unsigned long long ffma2(unsigned long long a,
                                                    unsigned long long b,
                                                    unsigned long long c) {
    unsigned long long d;
    asm("fma.rn.f32x2 %0, %1, %2, %3;" : "=l"(d) : "l"(a), "l"(b), "l"(c));
    return d;
}

// CAT 0 (t2i): eye ^ ((!pad && causal) || full)
// CAT 1 (lm):  causal
// CAT 2 (mmu): causal || kv <= 579
template <int CAT>
__device__ __forceinline__ bool mask_fn(int r, int kv, int pad_end, int fs, int fe) {
    if (CAT == 1) return r >= kv;
    if (CAT == 2) return (r >= kv) || (kv <= NCLIP3);
    bool pad    = kv < pad_end;
    bool causal = (!pad) && (r >= kv);
    bool full   = (kv >= fs) && (kv < fe);
    return ((r == kv) ? 1 : 0) ^ ((causal || full) ? 1 : 0);
}

template <int CAT>
__device__ __forceinline__ void process_tile(
    const float* __restrict__ Qs, const float* __restrict__ Ks,
    const float* __restrict__ Vs, float* __restrict__ Ps,
    const int* __restrict__ pads,
    unsigned long long (&O2)[8][4], float (&lacc)[8],
    int ty, int tx, int q0, int kv0,
    const int (&fs8)[8], const int (&fe8)[8])
{
    float rowsum[8];
#pragma unroll
    for (int i = 0; i < 8; ++i) rowsum[i] = 0.0f;

    // ---- GEMM1: S = Q K^T, contracted in f32x2 d-pairs, 2 kv-halves ----
#pragma unroll
    for (int h = 0; h < 2; ++h) {
        unsigned long long acc[8][4];
#pragma unroll
        for (int i = 0; i < 8; ++i)
#pragma unroll
            for (int j = 0; j < 4; ++j) acc[i][j] = 0ull;

#pragma unroll 4
        for (int dc = 0; dc < 16; ++dc) {
            const int d = dc * 4;
            ulonglong2 qv[8];
#pragma unroll
            for (int i = 0; i < 8; ++i)
                qv[i] = *reinterpret_cast<const ulonglong2*>(&Qs[(ty + 16 * i) * QPAD + d]);
            ulonglong2 kv4[4];
#pragma unroll
            for (int j = 0; j < 4; ++j)
                kv4[j] = *reinterpret_cast<const ulonglong2*>(&Ks[(tx + 8 * (h * 4 + j)) * QPAD + d]);
#pragma unroll
            for (int i = 0; i < 8; ++i)
#pragma unroll
                for (int j = 0; j < 4; ++j) {
                    acc[i][j] = ffma2(qv[i].x, kv4[j].x, acc[i][j]);
                    acc[i][j] = ffma2(qv[i].y, kv4[j].y, acc[i][j]);
                }
        }
        // epilogue: horizontal add, mask, exp, stage P
#pragma unroll
        for (int i = 0; i < 8; ++i) {
            const int r = q0 + ty + 16 * i;
#pragma unroll
            for (int j = 0; j < 4; ++j) {
                const int kvr = tx + 8 * (h * 4 + j);
                const int kv  = kv0 + kvr;
                float2 f = upk2(acc[i][j]);
                float s = f.x + f.y;
                int pe = (CAT == 0) ? pads[kvr] : 0;
                bool m = mask_fn<CAT>(r, kv, pe, fs8[i], fe8[i]);
                s = m ? s : MASKED_S;
                float p = __expf(s);
                rowsum[i] += p;
                Ps[(ty + 16 * i) * QPAD + kvr] = p;
            }
        }
    }

    // reduce row sums over the 8 tx-threads sharing each q row (lanes ty*8+tx)
#pragma unroll
    for (int i = 0; i < 8; ++i) {
        float rs = rowsum[i];
        rs += __shfl_xor_sync(0xffffffffu, rs, 1);
        rs += __shfl_xor_sync(0xffffffffu, rs, 2);
        rs += __shfl_xor_sync(0xffffffffu, rs, 4);
        lacc[i] += rs;
    }

    __syncthreads();   // P fully staged before GEMM2 reads

    // ---- GEMM2: O += P V, packed over d-pairs ----
#pragma unroll 4
    for (int kv = 0; kv < BN; ++kv) {
        unsigned long long pp[8];
#pragma unroll
        for (int i = 0; i < 8; ++i)
            pp[i] = pk2b(Ps[(ty + 16 * i) * QPAD + kv]);
        ulonglong2 va = *reinterpret_cast<const ulonglong2*>(&Vs[kv * QPAD + tx * 8]);
        ulonglong2 vb = *reinterpret_cast<const ulonglong2*>(&Vs[kv * QPAD + tx * 8 + 4]);
        unsigned long long v4[4] = { va.x, va.y, vb.x, vb.y };
#pragma unroll
        for (int i = 0; i < 8; ++i)
#pragma unroll
            for (int jp = 0; jp < 4; ++jp)
                O2[i][jp] = ffma2(pp[i], v4[jp], O2[i][jp]);
    }
}

__global__ void __launch_bounds__(BM)
omni_attn_kernel(const float* __restrict__ q,
                 const float* __restrict__ k,
                 const float* __restrict__ v,
                 const int* __restrict__ pad_ends,
                 const int* __restrict__ full_starts,
                 const int* __restrict__ full_ends,
                 const int* __restrict__ p_bt2i,
                 const int* __restrict__ p_blm,
                 float* __restrict__ out)
{
    extern __shared__ float sm[];
    float* Qs = sm;                       // [128][68]
    float* Ks = Qs + BM * QPAD;           // [64][68]
    float* Vs = Ks + BN * QPAD;           // [64][68]
    float* Ps = Vs + BN * QPAD;           // [128][68]
    int*   pads = (int*)(Ps + BM * QPAD); // [64]

    const int tid = threadIdx.x;
    const int ty  = tid >> 3;     // 0..15  -> q rows ty+16i
    const int tx  = tid & 7;      // 0..7   -> kv cols tx+8j / d cols tx*8..+7
    const int head = blockIdx.y;
    const int b    = head / HH;
    const int q0   = blockIdx.x * BM;

    const int bt2i = p_bt2i[0];
    const int blm  = p_blm[0];
    const int cat  = (b < bt2i) ? 0 : ((b < bt2i + blm) ? 1 : 2);

    // stage Q (pre-scaled by 1/sqrt(D))
    {
        const float4* qg = reinterpret_cast<const float4*>(q + ((size_t)head * SQ + q0) * DD);
#pragma unroll
        for (int it = 0; it < 16; ++it) {
            int idx = tid + it * BM;          // 0..2047
            int row = idx >> 4, c = idx & 15;
            float4 t = qg[idx];
            t.x *= 0.125f; t.y *= 0.125f; t.z *= 0.125f; t.w *= 0.125f;
            *reinterpret_cast<float4*>(&Qs[row * QPAD + c * 4]) = t;
        }
    }

    int fs8[8], fe8[8];
#pragma unroll
    for (int i = 0; i < 8; ++i) { fs8[i] = 0; fe8[i] = 0; }
    if (cat == 0) {
#pragma unroll
        for (int i = 0; i < 8; ++i) {
            int r = q0 + ty + 16 * i;
            fs8[i] = full_starts[r];
            fe8[i] = full_ends[r];
        }
    }

    unsigned long long O2[8][4];
#pragma unroll
    for (int i = 0; i < 8; ++i)
#pragma unroll
        for (int jp = 0; jp < 4; ++jp) O2[i][jp] = 0ull;
    float lacc[8];
#pragma unroll
    for (int i = 0; i < 8; ++i) lacc[i] = 0.0f;

    // kv-tile count (same skipping logic as before)
    int nt;
    if (cat == 0)      nt = SQ / BN;
    else if (cat == 1) nt = (q0 + BM) / BN;
    else {
        int ntc = (q0 + BM) / BN;
        int ntm = NCLIP3 / BN + 1;
        nt = (ntc > ntm) ? ntc : ntm;
        if (nt > SQ / BN) nt = SQ / BN;
    }

    const float* kbase  = k + (size_t)head * SQ * DD;
    const float* vbase  = v + (size_t)head * SQ * DD;
    const int*   padrow = pad_ends + b * SQ;

    for (int t = 0; t < nt; ++t) {
        const int kv0 = t * BN;
        __syncthreads();   // prior tile's P/V reads done
        {
            const float4* kg = reinterpret_cast<const float4*>(kbase + (size_t)kv0 * DD);
            const float4* vg = reinterpret_cast<const float4*>(vbase + (size_t)kv0 * DD);
#pragma unroll
            for (int it = 0; it < 8; ++it) {
                int idx = tid + it * BM;      // 0..1023
                int row = idx >> 4, c = idx & 15;
                *reinterpret_cast<float4*>(&Ks[row * QPAD + c * 4]) = kg[idx];
                *reinterpret_cast<float4*>(&Vs[row * QPAD + c * 4]) = vg[idx];
            }
            if (cat == 0 && tid < BN) pads[tid] = padrow[kv0 + tid];
        }
        __syncthreads();

        if (cat == 0)
            process_tile<0>(Qs, Ks, Vs, Ps, pads, O2, lacc, ty, tx, q0, kv0, fs8, fe8);
        else if (cat == 1)
            process_tile<1>(Qs, Ks, Vs, Ps, pads, O2, lacc, ty, tx, q0, kv0, fs8, fe8);
        else
            process_tile<2>(Qs, Ks, Vs, Ps, pads, O2, lacc, ty, tx, q0, kv0, fs8, fe8);
    }

    // ---- epilogue: normalize, store ----
#pragma unroll
    for (int i = 0; i < 8; ++i) {
        const float inv = 1.0f / lacc[i];
        const int r = q0 + ty + 16 * i;
        float* op = out + ((size_t)head * SQ + r) * DD + tx * 8;
        float2 a = upk2(O2[i][0]);
        float2 bb = upk2(O2[i][1]);
        float2 c = upk2(O2[i][2]);
        float2 d = upk2(O2[i][3]);
        float4 o0 = { a.x * inv, a.y * inv, bb.x * inv, bb.y * inv };
        float4 o1 = { c.x * inv, c.y * inv, d.x * inv, d.y * inv };
        *reinterpret_cast<float4*>(op)     = o0;
        *reinterpret_cast<float4*>(op + 4) = o1;
    }
}

extern "C" void kernel_launch(void* const* d_in, const int* in_sizes, int n_in,
                              void* d_out, int out_size) {
    const float* q  = (const float*)d_in[0];
    const float* k  = (const float*)d_in[1];
    const float* v  = (const float*)d_in[2];
    const int* pad_ends    = (const int*)d_in[3];
    const int* full_starts = (const int*)d_in[4];
    const int* full_ends   = (const int*)d_in[5];
    const int* bt2i        = (const int*)d_in[6];
    const int* blm         = (const int*)d_in[7];
    float* out = (float*)d_out;

    const size_t smem = (size_t)(BM * QPAD + BN * QPAD + BN * QPAD + BM * QPAD) * 4 + BN * 4;
    static int configured = 0;
    if (!configured) {
        cudaFuncSetAttribute(omni_attn_kernel,
                             cudaFuncAttributeMaxDynamicSharedMemorySize, (int)smem);
        configured = 1;
    }

    dim3 grid(SQ / BM, 12 * HH);
    dim3 block(BM);
    omni_attn_kernel<<<grid, block, smem>>>(q, k, v, pad_ends, full_starts, full_ends,
                                            bt2i, blm, out);
}

// round 7
// speedup vs baseline: 3.4087x; 2.4441x over previous
#include <cuda_runtime.h>
#include <cstdint>

#define SQ 1024
#define DD 64
#define HH 8
#define BM 128
#define BN 64
#define PQ 68           // pitch (floats) for Q, K, P tiles  (68 % 32 == 4)
#define PV 72           // pitch (floats) for V tile         (72 % 32 == 8)
#define NCLIP3 579
#define MASKED_L2 (-72.0f)
#define LOG2E 1.4426950408889634f

// smem layout in 32-bit words
#define O_Q   0                    // 128 x 68
#define O_K   (O_Q + BM * PQ)      // 64 x 68
#define O_V   (O_K + BN * PQ)      // 64 x 72
#define O_P   (O_V + BN * PV)      // 128 x 68
#define O_PAD (O_P + BM * PQ)      // 64 ints
#define SMEM_WORDS (O_PAD + BN)
#define SMEM_BYTES (SMEM_WORDS * 4)

static __device__ __forceinline__ uint32_t f2tf(float x) {
    uint32_t r;
    asm("cvt.rna.tf32.f32 %0, %1;" : "=r"(r) : "f"(x));
    return r;
}
static __device__ __forceinline__ float ex2f(float x) {
    float r;
    asm("ex2.approx.f32 %0, %1;" : "=f"(r) : "f"(x));
    return r;
}
static __device__ __forceinline__ void mma_tf32(float* c, const uint32_t* a,
                                                const uint32_t* b) {
    asm volatile(
        "mma.sync.aligned.m16n8k8.row.col.f32.tf32.tf32.f32 "
        "{%0,%1,%2,%3}, {%4,%5,%6,%7}, {%8,%9}, {%0,%1,%2,%3};"
        : "+f"(c[0]), "+f"(c[1]), "+f"(c[2]), "+f"(c[3])
        : "r"(a[0]), "r"(a[1]), "r"(a[2]), "r"(a[3]), "r"(b[0]), "r"(b[1]));
}

// CAT 0 (t2i): eye ^ ((!pad && causal) || full)
// CAT 1 (lm):  causal ; CAT 2 (mmu): causal || kv<=579
template <int CAT>
static __device__ __forceinline__ bool mask_fn(int r, int kv, int pad_end,
                                               int fs, int fe) {
    if (CAT == 1) return r >= kv;
    if (CAT == 2) return (r >= kv) || (kv <= NCLIP3);
    bool pad    = kv < pad_end;
    bool causal = (!pad) && (r >= kv);
    bool full   = (kv >= fs) && (kv < fe);
    return ((r == kv) ? 1 : 0) ^ ((causal || full) ? 1 : 0);
}

template <int CAT>
static __device__ __forceinline__ void attn_loop(
    uint32_t* __restrict__ sm,
    const float* kbase, const float* vbase, const int* padrow,
    int nt_count, int q0, int tid, int m0, int g, int t,
    const int (&fs4)[4], const int (&fe4)[4],
    float (&oacc)[2][8][4], float (&lacc)[4])
{
    uint32_t* Qs = sm + O_Q;
    uint32_t* Ks = sm + O_K;
    uint32_t* Vs = sm + O_V;
    uint32_t* Ps = sm + O_P;
    int*      pads = (int*)(sm + O_PAD);

    for (int tt = 0; tt < nt_count; ++tt) {
        const int kv0 = tt * BN;
        __syncthreads();   // previous GEMM2 finished reading Ks/Vs/Ps

        // ---- stage K (pitch PQ) and V (pitch PV), tf32-converted ----
        {
            const float4* kg = reinterpret_cast<const float4*>(kbase + (size_t)kv0 * DD);
            const float4* vg = reinterpret_cast<const float4*>(vbase + (size_t)kv0 * DD);
#pragma unroll
            for (int it = 0; it < 8; ++it) {
                int idx = tid + it * BM;           // 0..1023
                int row = idx >> 4, c4 = idx & 15;
                float4 kvl = kg[idx];
                uint4 ku = { f2tf(kvl.x), f2tf(kvl.y), f2tf(kvl.z), f2tf(kvl.w) };
                *reinterpret_cast<uint4*>(&Ks[row * PQ + c4 * 4]) = ku;
                float4 vvl = vg[idx];
                uint4 vu = { f2tf(vvl.x), f2tf(vvl.y), f2tf(vvl.z), f2tf(vvl.w) };
                *reinterpret_cast<uint4*>(&Vs[row * PV + c4 * 4]) = vu;
            }
            if (CAT == 0 && tid < BN) pads[tid] = padrow[kv0 + tid];
        }
        __syncthreads();

        // ---- GEMM1: S = Q K^T  (tf32 mma, S in fragments) ----
        float sacc[2][8][4];
#pragma unroll
        for (int mt = 0; mt < 2; ++mt)
#pragma unroll
            for (int nt = 0; nt < 8; ++nt)
#pragma unroll
                for (int u = 0; u < 4; ++u) sacc[mt][nt][u] = 0.0f;

#pragma unroll
        for (int kk = 0; kk < 8; ++kk) {
            uint32_t a[2][4];
#pragma unroll
            for (int mt = 0; mt < 2; ++mt) {
                const uint32_t* qb = Qs + (m0 + mt * 16) * PQ + kk * 8;
                a[mt][0] = qb[g * PQ + t];
                a[mt][1] = qb[(g + 8) * PQ + t];
                a[mt][2] = qb[g * PQ + t + 4];
                a[mt][3] = qb[(g + 8) * PQ + t + 4];
            }
#pragma unroll
            for (int nt = 0; nt < 8; ++nt) {
                uint32_t b[2];
                const uint32_t* kb = Ks + (nt * 8 + g) * PQ + kk * 8;
                b[0] = kb[t];
                b[1] = kb[t + 4];
                mma_tf32(sacc[0][nt], a[0], b);
                mma_tf32(sacc[1][nt], a[1], b);
            }
        }

        // ---- epilogue: mask + exp2 + rowsum + stage P (tf32) ----
        float rs[4] = {0.0f, 0.0f, 0.0f, 0.0f};
#pragma unroll
        for (int mt = 0; mt < 2; ++mt) {
            const int r0 = q0 + m0 + mt * 16 + g;
            const int r1 = r0 + 8;
#pragma unroll
            for (int nt = 0; nt < 8; ++nt) {
                const int kvA = kv0 + nt * 8 + 2 * t;
                const int kvB = kvA + 1;
                int peA = 0, peB = 0;
                if (CAT == 0) {
                    int2 pe2 = *reinterpret_cast<const int2*>(&pads[nt * 8 + 2 * t]);
                    peA = pe2.x; peB = pe2.y;
                }
                float s0 = mask_fn<CAT>(r0, kvA, peA, fs4[mt * 2 + 0], fe4[mt * 2 + 0]) ? sacc[mt][nt][0] : MASKED_L2;
                float s1 = mask_fn<CAT>(r0, kvB, peB, fs4[mt * 2 + 0], fe4[mt * 2 + 0]) ? sacc[mt][nt][1] : MASKED_L2;
                float s2 = mask_fn<CAT>(r1, kvA, peA, fs4[mt * 2 + 1], fe4[mt * 2 + 1]) ? sacc[mt][nt][2] : MASKED_L2;
                float s3 = mask_fn<CAT>(r1, kvB, peB, fs4[mt * 2 + 1], fe4[mt * 2 + 1]) ? sacc[mt][nt][3] : MASKED_L2;
                float p0 = ex2f(s0), p1 = ex2f(s1), p2 = ex2f(s2), p3 = ex2f(s3);
                rs[mt * 2 + 0] += p0 + p1;
                rs[mt * 2 + 1] += p2 + p3;
                uint2 w0 = { f2tf(p0), f2tf(p1) };
                uint2 w1 = { f2tf(p2), f2tf(p3) };
                *reinterpret_cast<uint2*>(&Ps[(m0 + mt * 16 + g) * PQ + nt * 8 + 2 * t]) = w0;
                *reinterpret_cast<uint2*>(&Ps[(m0 + mt * 16 + g + 8) * PQ + nt * 8 + 2 * t]) = w1;
            }
        }
#pragma unroll
        for (int i = 0; i < 4; ++i) {
            float v = rs[i];
            v += __shfl_xor_sync(0xffffffffu, v, 1);
            v += __shfl_xor_sync(0xffffffffu, v, 2);
            lacc[i] += v;
        }
        __syncthreads();   // P staged before GEMM2 reads

        // ---- GEMM2: O += P V ----
#pragma unroll
        for (int kk = 0; kk < 8; ++kk) {
            uint32_t a[2][4];
#pragma unroll
            for (int mt = 0; mt < 2; ++mt) {
                const uint32_t* pb = Ps + (m0 + mt * 16) * PQ + kk * 8;
                a[mt][0] = pb[g * PQ + t];
                a[mt][1] = pb[(g + 8) * PQ + t];
                a[mt][2] = pb[g * PQ + t + 4];
                a[mt][3] = pb[(g + 8) * PQ + t + 4];
            }
#pragma unroll
            for (int nt = 0; nt < 8; ++nt) {
                uint32_t b[2];
                b[0] = Vs[(kk * 8 + t) * PV + nt * 8 + g];
                b[1] = Vs[(kk * 8 + t + 4) * PV + nt * 8 + g];
                mma_tf32(oacc[0][nt], a[0], b);
                mma_tf32(oacc[1][nt], a[1], b);
            }
        }
    }
}

__global__ void __launch_bounds__(BM)
omni_attn_mma(const float* __restrict__ q,
              const float* __restrict__ k,
              const float* __restrict__ v,
              const int* __restrict__ pad_ends,
              const int* __restrict__ full_starts,
              const int* __restrict__ full_ends,
              const int* __restrict__ p_bt2i,
              const int* __restrict__ p_blm,
              float* __restrict__ out)
{
    extern __shared__ uint32_t sm[];

    const int tid  = threadIdx.x;
    const int wid  = tid >> 5;
    const int lane = tid & 31;
    const int g    = lane >> 2;       // 0..7
    const int t    = lane & 3;        // 0..3
    const int m0   = wid * 32;        // warp's q-row base within tile
    const int head = blockIdx.y;
    const int b    = head / HH;
    const int q0   = blockIdx.x * BM;

    const int bt2i = p_bt2i[0];
    const int blm  = p_blm[0];
    const int cat  = (b < bt2i) ? 0 : ((b < bt2i + blm) ? 1 : 2);

    // ---- stage Q once: scaled to log2 domain, tf32 bits, pitch PQ ----
    {
        const float sc = 0.125f * LOG2E;
        const float4* qg = reinterpret_cast<const float4*>(q + ((size_t)head * SQ + q0) * DD);
#pragma unroll
        for (int it = 0; it < 16; ++it) {
            int idx = tid + it * BM;          // 0..2047
            int row = idx >> 4, c4 = idx & 15;
            float4 tq = qg[idx];
            uint4 u = { f2tf(tq.x * sc), f2tf(tq.y * sc), f2tf(tq.z * sc), f2tf(tq.w * sc) };
            *reinterpret_cast<uint4*>(&sm[O_Q + row * PQ + c4 * 4]) = u;
        }
    }

    int fs4[4] = {0, 0, 0, 0}, fe4[4] = {0, 0, 0, 0};
    if (cat == 0) {
#pragma unroll
        for (int mt = 0; mt < 2; ++mt)
#pragma unroll
            for (int h = 0; h < 2; ++h) {
                int r = q0 + m0 + mt * 16 + g + h * 8;
                fs4[mt * 2 + h] = full_starts[r];
                fe4[mt * 2 + h] = full_ends[r];
            }
    }

    float oacc[2][8][4];
#pragma unroll
    for (int mt = 0; mt < 2; ++mt)
#pragma unroll
        for (int nt = 0; nt < 8; ++nt)
#pragma unroll
            for (int u = 0; u < 4; ++u) oacc[mt][nt][u] = 0.0f;
    float lacc[4] = {0.0f, 0.0f, 0.0f, 0.0f};

    int ntc_full;
    if (cat == 0)      ntc_full = SQ / BN;
    else if (cat == 1) ntc_full = (q0 + BM) / BN;
    else {
        int ntc = (q0 + BM) / BN;
        int ntm = NCLIP3 / BN + 1;
        ntc_full = (ntc > ntm) ? ntc : ntm;
        if (ntc_full > SQ / BN) ntc_full = SQ / BN;
    }

    const float* kbase  = k + (size_t)head * SQ * DD;
    const float* vbase  = v + (size_t)head * SQ * DD;
    const int*   padrow = pad_ends + b * SQ;

    if (cat == 0)
        attn_loop<0>(sm, kbase, vbase, padrow, ntc_full, q0, tid, m0, g, t, fs4, fe4, oacc, lacc);
    else if (cat == 1)
        attn_loop<1>(sm, kbase, vbase, padrow, ntc_full, q0, tid, m0, g, t, fs4, fe4, oacc, lacc);
    else
        attn_loop<2>(sm, kbase, vbase, padrow, ntc_full, q0, tid, m0, g, t, fs4, fe4, oacc, lacc);

    // ---- epilogue: normalize fragments and store ----
#pragma unroll
    for (int mt = 0; mt < 2; ++mt)
#pragma unroll
        for (int h = 0; h < 2; ++h) {
            const float inv = 1.0f / lacc[mt * 2 + h];
            const int r = q0 + m0 + mt * 16 + g + h * 8;
            float* op = out + ((size_t)head * SQ + r) * DD;
#pragma unroll
            for (int nt = 0; nt < 8; ++nt) {
                float2 o;
                o.x = oacc[mt][nt][h * 2 + 0] * inv;
                o.y = oacc[mt][nt][h * 2 + 1] * inv;
                *reinterpret_cast<float2*>(op + nt * 8 + 2 * t) = o;
            }
        }
}

extern "C" void kernel_launch(void* const* d_in, const int* in_sizes, int n_in,
                              void* d_out, int out_size) {
    const float* q  = (const float*)d_in[0];
    const float* k  = (const float*)d_in[1];
    const float* v  = (const float*)d_in[2];
    const int* pad_ends    = (const int*)d_in[3];
    const int* full_starts = (const int*)d_in[4];
    const int* full_ends   = (const int*)d_in[5];
    const int* bt2i        = (const int*)d_in[6];
    const int* blm         = (const int*)d_in[7];
    float* out = (float*)d_out;

    static int configured = 0;
    if (!configured) {
        cudaFuncSetAttribute(omni_attn_mma,
                             cudaFuncAttributeMaxDynamicSharedMemorySize, SMEM_BYTES);
        configured = 1;
    }

    dim3 grid(SQ / BM, 12 * HH);
    dim3 block(BM);
    omni_attn_mma<<<grid, block, SMEM_BYTES>>>(q, k, v, pad_ends, full_starts, full_ends,
                                               bt2i, blm, out);
}

// round 9
// speedup vs baseline: 3.6531x; 1.0717x over previous
#include <cuda_runtime.h>
#include <cstdint>

#define SQ 1024
#define DD 64
#define HH 8
#define BM 128
#define BN 64
#define NT 256          // threads per block (8 warps)
#define PQ 68           // pitch (floats) for Q, K, P tiles  (68 % 32 == 4)
#define PV 72           // pitch (floats) for V tile         (72 % 32 == 8)
#define NCLIP3 579
#define MASKED_L2 (-72.0f)
#define LOG2E 1.4426950408889634f

// smem layout in 32-bit words
#define O_Q   0                    // 128 x 68
#define O_K   (O_Q + BM * PQ)      // 64 x 68
#define O_V   (O_K + BN * PQ)      // 64 x 72
#define O_P   (O_V + BN * PV)      // 128 x 68
#define O_PAD (O_P + BM * PQ)      // 64 ints
#define SMEM_WORDS (O_PAD + BN)
#define SMEM_BYTES (SMEM_WORDS * 4)

static __device__ __forceinline__ uint32_t f2tf(float x) {
    uint32_t r;
    asm("cvt.rna.tf32.f32 %0, %1;" : "=r"(r) : "f"(x));
    return r;
}
static __device__ __forceinline__ float ex2f(float x) {
    float r;
    asm("ex2.approx.f32 %0, %1;" : "=f"(r) : "f"(x));
    return r;
}
static __device__ __forceinline__ void mma_tf32(float* c, const uint32_t* a,
                                                const uint32_t* b) {
    asm volatile(
        "mma.sync.aligned.m16n8k8.row.col.f32.tf32.tf32.f32 "
        "{%0,%1,%2,%3}, {%4,%5,%6,%7}, {%8,%9}, {%0,%1,%2,%3};"
        : "+f"(c[0]), "+f"(c[1]), "+f"(c[2]), "+f"(c[3])
        : "r"(a[0]), "r"(a[1]), "r"(a[2]), "r"(a[3]), "r"(b[0]), "r"(b[1]));
}

// CAT 0 (t2i): eye ^ ((!pad && causal) || full)
// CAT 1 (lm):  causal ; CAT 2 (mmu): causal || kv<=579
template <int CAT>
static __device__ __forceinline__ bool mask_fn(int r, int kv, int pad_end,
                                               int fs, int fe) {
    if (CAT == 1) return r >= kv;
    if (CAT == 2) return (r >= kv) || (kv <= NCLIP3);
    bool pad    = kv < pad_end;
    bool causal = (!pad) && (r >= kv);
    bool full   = (kv >= fs) && (kv < fe);
    return ((r == kv) ? 1 : 0) ^ ((causal || full) ? 1 : 0);
}

template <int CAT>
static __device__ __forceinline__ void attn_loop(
    uint32_t* __restrict__ sm,
    const float* kbase, const float* vbase, const int* padrow,
    int nt_count, int q0, int tid, int m0, int g, int t,
    const int (&fs2)[2], const int (&fe2)[2],
    float (&oacc)[8][4], float (&lacc)[2])
{
    uint32_t* Qs = sm + O_Q;
    uint32_t* Ks = sm + O_K;
    uint32_t* Vs = sm + O_V;
    uint32_t* Ps = sm + O_P;
    int*      pads = (int*)(sm + O_PAD);

    for (int tt = 0; tt < nt_count; ++tt) {
        const int kv0 = tt * BN;
        __syncthreads();   // previous GEMM2 finished reading Ks/Vs/Ps

        // ---- stage K (pitch PQ) and V (pitch PV), tf32-converted ----
        {
            const float4* kg = reinterpret_cast<const float4*>(kbase + (size_t)kv0 * DD);
            const float4* vg = reinterpret_cast<const float4*>(vbase + (size_t)kv0 * DD);
#pragma unroll
            for (int it = 0; it < 4; ++it) {
                int idx = tid + it * NT;           // 0..1023
                int row = idx >> 4, c4 = idx & 15;
                float4 kvl = kg[idx];
                uint4 ku = { f2tf(kvl.x), f2tf(kvl.y), f2tf(kvl.z), f2tf(kvl.w) };
                *reinterpret_cast<uint4*>(&Ks[row * PQ + c4 * 4]) = ku;
                float4 vvl = vg[idx];
                uint4 vu = { f2tf(vvl.x), f2tf(vvl.y), f2tf(vvl.z), f2tf(vvl.w) };
                *reinterpret_cast<uint4*>(&Vs[row * PV + c4 * 4]) = vu;
            }
            if (CAT == 0 && tid < BN) pads[tid] = padrow[kv0 + tid];
        }
        __syncthreads();

        // ---- GEMM1: S = Q K^T  (tf32 mma, S in fragments) ----
        float sacc[8][4];
#pragma unroll
        for (int nt = 0; nt < 8; ++nt)
#pragma unroll
            for (int u = 0; u < 4; ++u) sacc[nt][u] = 0.0f;

#pragma unroll
        for (int kk = 0; kk < 8; ++kk) {
            uint32_t a[4];
            const uint32_t* qb = Qs + m0 * PQ + kk * 8;
            a[0] = qb[g * PQ + t];
            a[1] = qb[(g + 8) * PQ + t];
            a[2] = qb[g * PQ + t + 4];
            a[3] = qb[(g + 8) * PQ + t + 4];
#pragma unroll
            for (int nt = 0; nt < 8; ++nt) {
                uint32_t b[2];
                const uint32_t* kb = Ks + (nt * 8 + g) * PQ + kk * 8;
                b[0] = kb[t];
                b[1] = kb[t + 4];
                mma_tf32(sacc[nt], a, b);
            }
        }

        // ---- epilogue: mask + exp2 + rowsum + stage P (tf32) ----
        float rs0 = 0.0f, rs1 = 0.0f;
        {
            const int r0 = q0 + m0 + g;
            const int r1 = r0 + 8;
#pragma unroll
            for (int nt = 0; nt < 8; ++nt) {
                const int kvA = kv0 + nt * 8 + 2 * t;
                const int kvB = kvA + 1;
                int peA = 0, peB = 0;
                if (CAT == 0) {
                    int2 pe2 = *reinterpret_cast<const int2*>(&pads[nt * 8 + 2 * t]);
                    peA = pe2.x; peB = pe2.y;
                }
                float s0 = mask_fn<CAT>(r0, kvA, peA, fs2[0], fe2[0]) ? sacc[nt][0] : MASKED_L2;
                float s1 = mask_fn<CAT>(r0, kvB, peB, fs2[0], fe2[0]) ? sacc[nt][1] : MASKED_L2;
                float s2 = mask_fn<CAT>(r1, kvA, peA, fs2[1], fe2[1]) ? sacc[nt][2] : MASKED_L2;
                float s3 = mask_fn<CAT>(r1, kvB, peB, fs2[1], fe2[1]) ? sacc[nt][3] : MASKED_L2;
                float p0 = ex2f(s0), p1 = ex2f(s1), p2 = ex2f(s2), p3 = ex2f(s3);
                rs0 += p0 + p1;
                rs1 += p2 + p3;
                uint2 w0 = { f2tf(p0), f2tf(p1) };
                uint2 w1 = { f2tf(p2), f2tf(p3) };
                *reinterpret_cast<uint2*>(&Ps[(m0 + g) * PQ + nt * 8 + 2 * t]) = w0;
                *reinterpret_cast<uint2*>(&Ps[(m0 + g + 8) * PQ + nt * 8 + 2 * t]) = w1;
            }
        }
        rs0 += __shfl_xor_sync(0xffffffffu, rs0, 1);
        rs0 += __shfl_xor_sync(0xffffffffu, rs0, 2);
        rs1 += __shfl_xor_sync(0xffffffffu, rs1, 1);
        rs1 += __shfl_xor_sync(0xffffffffu, rs1, 2);
        lacc[0] += rs0;
        lacc[1] += rs1;
        __syncthreads();   // P staged before GEMM2 reads

        // ---- GEMM2: O += P V ----
#pragma unroll
        for (int kk = 0; kk < 8; ++kk) {
            uint32_t a[4];
            const uint32_t* pb = Ps + m0 * PQ + kk * 8;
            a[0] = pb[g * PQ + t];
            a[1] = pb[(g + 8) * PQ + t];
            a[2] = pb[g * PQ + t + 4];
            a[3] = pb[(g + 8) * PQ + t + 4];
#pragma unroll
            for (int nt = 0; nt < 8; ++nt) {
                uint32_t b[2];
                b[0] = Vs[(kk * 8 + t) * PV + nt * 8 + g];
                b[1] = Vs[(kk * 8 + t + 4) * PV + nt * 8 + g];
                mma_tf32(oacc[nt], a, b);
            }
        }
    }
}

__global__ void __launch_bounds__(NT)
omni_attn_mma(const float* __restrict__ q,
              const float* __restrict__ k,
              const float* __restrict__ v,
              const int* __restrict__ pad_ends,
              const int* __restrict__ full_starts,
              const int* __restrict__ full_ends,
              const int* __restrict__ p_bt2i,
              const int* __restrict__ p_blm,
              float* __restrict__ out)
{
    extern __shared__ uint32_t sm[];

    const int tid  = threadIdx.x;
    const int wid  = tid >> 5;        // 0..7
    const int lane = tid & 31;
    const int g    = lane >> 2;       // 0..7
    const int t    = lane & 3;        // 0..3
    const int m0   = wid * 16;        // warp's q-row base within tile
    const int head = blockIdx.y;
    const int b    = head / HH;
    const int q0   = blockIdx.x * BM;

    const int bt2i = p_bt2i[0];
    const int blm  = p_blm[0];
    const int cat  = (b < bt2i) ? 0 : ((b < bt2i + blm) ? 1 : 2);

    // ---- stage Q once: scaled to log2 domain, tf32 bits, pitch PQ ----
    {
        const float sc = 0.125f * LOG2E;
        const float4* qg = reinterpret_cast<const float4*>(q + ((size_t)head * SQ + q0) * DD);
#pragma unroll
        for (int it = 0; it < 8; ++it) {
            int idx = tid + it * NT;          // 0..2047
            int row = idx >> 4, c4 = idx & 15;
            float4 tq = qg[idx];
            uint4 u = { f2tf(tq.x * sc), f2tf(tq.y * sc), f2tf(tq.z * sc), f2tf(tq.w * sc) };
            *reinterpret_cast<uint4*>(&sm[O_Q + row * PQ + c4 * 4]) = u;
        }
    }

    int fs2[2] = {0, 0}, fe2[2] = {0, 0};
    if (cat == 0) {
#pragma unroll
        for (int h = 0; h < 2; ++h) {
            int r = q0 + m0 + g + h * 8;
            fs2[h] = full_starts[r];
            fe2[h] = full_ends[r];
        }
    }

    float oacc[8][4];
#pragma unroll
    for (int nt = 0; nt < 8; ++nt)
#pragma unroll
        for (int u = 0; u < 4; ++u) oacc[nt][u] = 0.0f;
    float lacc[2] = {0.0f, 0.0f};

    int ntc_full;
    if (cat == 0)      ntc_full = SQ / BN;
    else if (cat == 1) ntc_full = (q0 + BM) / BN;
    else {
        int ntc = (q0 + BM) / BN;
        int ntm = NCLIP3 / BN + 1;
        ntc_full = (ntc > ntm) ? ntc : ntm;
        if (ntc_full > SQ / BN) ntc_full = SQ / BN;
    }

    const float* kbase  = k + (size_t)head * SQ * DD;
    const float* vbase  = v + (size_t)head * SQ * DD;
    const int*   padrow = pad_ends + b * SQ;

    if (cat == 0)
        attn_loop<0>(sm, kbase, vbase, padrow, ntc_full, q0, tid, m0, g, t, fs2, fe2, oacc, lacc);
    else if (cat == 1)
        attn_loop<1>(sm, kbase, vbase, padrow, ntc_full, q0, tid, m0, g, t, fs2, fe2, oacc, lacc);
    else
        attn_loop<2>(sm, kbase, vbase, padrow, ntc_full, q0, tid, m0, g, t, fs2, fe2, oacc, lacc);

    // ---- epilogue: normalize fragments and store ----
#pragma unroll
    for (int h = 0; h < 2; ++h) {
        const float inv = 1.0f / lacc[h];
        const int r = q0 + m0 + g + h * 8;
        float* op = out + ((size_t)head * SQ + r) * DD;
#pragma unroll
        for (int nt = 0; nt < 8; ++nt) {
            float2 o;
            o.x = oacc[nt][h * 2 + 0] * inv;
            o.y = oacc[nt][h * 2 + 1] * inv;
            *reinterpret_cast<float2*>(op + nt * 8 + 2 * t) = o;
        }
    }
}

extern "C" void kernel_launch(void* const* d_in, const int* in_sizes, int n_in,
                              void* d_out, int out_size) {
    const float* q  = (const float*)d_in[0];
    const float* k  = (const float*)d_in[1];
    const float* v  = (const float*)d_in[2];
    const int* pad_ends    = (const int*)d_in[3];
    const int* full_starts = (const int*)d_in[4];
    const int* full_ends   = (const int*)d_in[5];
    const int* bt2i        = (const int*)d_in[6];
    const int* blm         = (const int*)d_in[7];
    float* out = (float*)d_out;

    static int configured = 0;
    if (!configured) {
        cudaFuncSetAttribute(omni_attn_mma,
                             cudaFuncAttributeMaxDynamicSharedMemorySize, SMEM_BYTES);
        configured = 1;
    }

    dim3 grid(SQ / BM, 12 * HH);
    dim3 block(NT);
    omni_attn_mma<<<grid, block, SMEM_BYTES>>>(q, k, v, pad_ends, full_starts, full_ends,
                                               bt2i, blm, out);
}

// round 13
// speedup vs baseline: 3.6663x; 1.0036x over previous
#include <cuda_runtime.h>
#include <cstdint>

#define SQ 1024
#define DD 64
#define HH 8
#define BM 128
#define BN 64
#define NTH 256         // 8 warps
#define PQ 68           // pitch (words) for Q and K tiles (68 % 32 == 4)
#define PT 68           // pitch (words) for Vt tile
#define NCLIP3 579
#define MASKED_L2 (-72.0f)
#define LOG2E 1.4426950408889634f

// smem layout in 32-bit words
#define O_Q   0                    // 128 x 68
#define O_K   (BM * PQ)            // 64 x 68
#define O_T   (O_K + BN * PQ)      // Vt: 64 x 68
#define O_PAD (O_T + DD * PT)      // 64 ints
#define SMEM_WORDS (O_PAD + BN)
#define SMEM_BYTES (SMEM_WORDS * 4)

static __device__ __forceinline__ uint32_t f2tf(float x) {
    uint32_t r;
    asm("cvt.rna.tf32.f32 %0, %1;" : "=r"(r) : "f"(x));
    return r;
}
static __device__ __forceinline__ float ex2f(float x) {
    float r;
    asm("ex2.approx.f32 %0, %1;" : "=f"(r) : "f"(x));
    return r;
}
static __device__ __forceinline__ void mma_tf32(float* c, const uint32_t* a,
                                                const uint32_t* b) {
    asm volatile(
        "mma.sync.aligned.m16n8k8.row.col.f32.tf32.tf32.f32 "
        "{%0,%1,%2,%3}, {%4,%5,%6,%7}, {%8,%9}, {%0,%1,%2,%3};"
        : "+f"(c[0]), "+f"(c[1]), "+f"(c[2]), "+f"(c[3])
        : "r"(a[0]), "r"(a[1]), "r"(a[2]), "r"(a[3]), "r"(b[0]), "r"(b[1]));
}
static __device__ __forceinline__ void ldsm4(uint32_t& r0, uint32_t& r1,
                                             uint32_t& r2, uint32_t& r3,
                                             uint32_t addr) {
    asm volatile("ldmatrix.sync.aligned.m8n8.x4.shared.b16 {%0,%1,%2,%3}, [%4];"
                 : "=r"(r0), "=r"(r1), "=r"(r2), "=r"(r3) : "r"(addr));
}
static __device__ __forceinline__ uint32_t smem_u32(const void* p) {
    uint32_t a;
    asm("{ .reg .u64 t; cvta.to.shared.u64 t, %1; cvt.u32.u64 %0, t; }" : "=r"(a) : "l"(p));
    return a;
}

// CAT 0 (t2i): eye ^ ((!pad && causal) || full)
// CAT 1 (lm):  causal ; CAT 2 (mmu): causal || kv<=579
template <int CAT>
static __device__ __forceinline__ bool mask_fn(int r, int kv, int pad_end,
                                               int fs, int fe) {
    if (CAT == 1) return r >= kv;
    if (CAT == 2) return (r >= kv) || (kv <= NCLIP3);
    bool pad    = kv < pad_end;
    bool causal = (!pad) && (r >= kv);
    bool full   = (kv >= fs) && (kv < fe);
    return ((r == kv) ? 1 : 0) ^ ((causal || full) ? 1 : 0);
}

template <int CAT>
static __device__ __forceinline__ void attn_loop(
    uint32_t* __restrict__ sm,
    uint32_t qladdr, uint32_t kladdr, uint32_t tladdr,
    const float* kbase, const float* vbase, const int* padrow,
    int nt_count, int q0, int tid, int m0, int g, int t,
    const int (&fs2)[2], const int (&fe2)[2],
    float (&oacc)[8][4], float (&lacc)[2])
{
    uint32_t* Ks = sm + O_K;
    uint32_t* Ts = sm + O_T;
    int*      pads = (int*)(sm + O_PAD);

    const int lane = tid & 31;
    const int src0 = (lane & 28) | (t >> 1);
    const int src2 = src0 + 2;
    const bool odd = (t & 1) != 0;

    for (int tt = 0; tt < nt_count; ++tt) {
        const int kv0 = tt * BN;
        __syncthreads();   // previous GEMM2 finished reading Ks/Ts

        // ---- stage K (pitch PQ) and V transposed (pitch PT), tf32 ----
        {
            const float4* kg = reinterpret_cast<const float4*>(kbase + (size_t)kv0 * DD);
            const float4* vg = reinterpret_cast<const float4*>(vbase + (size_t)kv0 * DD);
#pragma unroll
            for (int it = 0; it < 4; ++it) {
                int idx = tid + it * NTH;          // 0..1023
                int row = idx >> 4, c4 = idx & 15;
                float4 kvl = kg[idx];
                uint4 ku = { f2tf(kvl.x), f2tf(kvl.y), f2tf(kvl.z), f2tf(kvl.w) };
                *reinterpret_cast<uint4*>(&Ks[row * PQ + c4 * 4]) = ku;
                float4 vvl = vg[idx];              // V[kv=row][d=4c4..4c4+3]
                Ts[(4 * c4 + 0) * PT + row] = f2tf(vvl.x);
                Ts[(4 * c4 + 1) * PT + row] = f2tf(vvl.y);
                Ts[(4 * c4 + 2) * PT + row] = f2tf(vvl.z);
                Ts[(4 * c4 + 3) * PT + row] = f2tf(vvl.w);
            }
            if (CAT == 0 && tid < BN) pads[tid] = padrow[kv0 + tid];
        }
        __syncthreads();

        // ---- GEMM1: S = Q K^T ----
        float sacc[8][4];
#pragma unroll
        for (int nt = 0; nt < 8; ++nt)
#pragma unroll
            for (int u = 0; u < 4; ++u) sacc[nt][u] = 0.0f;

#pragma unroll
        for (int kk = 0; kk < 8; ++kk) {
            uint32_t a[4];
            ldsm4(a[0], a[1], a[2], a[3], qladdr + kk * 32);
#pragma unroll
            for (int ntp = 0; ntp < 4; ++ntp) {
                uint32_t k0, k1, k2, k3;
                ldsm4(k0, k1, k2, k3, kladdr + ntp * (PQ * 64) + kk * 32);
                uint32_t b0[2] = { k0, k1 };
                mma_tf32(sacc[2 * ntp], a, b0);
                uint32_t b1[2] = { k2, k3 };
                mma_tf32(sacc[2 * ntp + 1], a, b1);
            }
        }

        // ---- epilogue: mask + exp2 + rowsum (P stays in regs) ----
        float rs0 = 0.0f, rs1 = 0.0f;
        {
            const int r0 = q0 + m0 + g;
            const int r1 = r0 + 8;
#pragma unroll
            for (int nt = 0; nt < 8; ++nt) {
                const int kvA = kv0 + nt * 8 + 2 * t;
                const int kvB = kvA + 1;
                int peA = 0, peB = 0;
                if (CAT == 0) {
                    int2 pe2 = *reinterpret_cast<const int2*>(&pads[nt * 8 + 2 * t]);
                    peA = pe2.x; peB = pe2.y;
                }
                float s0 = mask_fn<CAT>(r0, kvA, peA, fs2[0], fe2[0]) ? sacc[nt][0] : MASKED_L2;
                float s1 = mask_fn<CAT>(r0, kvB, peB, fs2[0], fe2[0]) ? sacc[nt][1] : MASKED_L2;
                float s2 = mask_fn<CAT>(r1, kvA, peA, fs2[1], fe2[1]) ? sacc[nt][2] : MASKED_L2;
                float s3 = mask_fn<CAT>(r1, kvB, peB, fs2[1], fe2[1]) ? sacc[nt][3] : MASKED_L2;
                float p0 = ex2f(s0), p1 = ex2f(s1), p2 = ex2f(s2), p3 = ex2f(s3);
                rs0 += p0 + p1;
                rs1 += p2 + p3;
                sacc[nt][0] = p0; sacc[nt][1] = p1;
                sacc[nt][2] = p2; sacc[nt][3] = p3;
            }
        }
        rs0 += __shfl_xor_sync(0xffffffffu, rs0, 1);
        rs0 += __shfl_xor_sync(0xffffffffu, rs0, 2);
        rs1 += __shfl_xor_sync(0xffffffffu, rs1, 1);
        rs1 += __shfl_xor_sync(0xffffffffu, rs1, 2);
        lacc[0] += rs0;
        lacc[1] += rs1;

        // ---- GEMM2: O += P V  (A-frag built via quad shuffles) ----
#pragma unroll
        for (int kk = 0; kk < 8; ++kk) {
            float q00 = __shfl_sync(0xffffffffu, sacc[kk][0], src0);
            float q01 = __shfl_sync(0xffffffffu, sacc[kk][1], src0);
            float q10 = __shfl_sync(0xffffffffu, sacc[kk][2], src0);
            float q11 = __shfl_sync(0xffffffffu, sacc[kk][3], src0);
            float q20 = __shfl_sync(0xffffffffu, sacc[kk][0], src2);
            float q21 = __shfl_sync(0xffffffffu, sacc[kk][1], src2);
            float q30 = __shfl_sync(0xffffffffu, sacc[kk][2], src2);
            float q31 = __shfl_sync(0xffffffffu, sacc[kk][3], src2);
            uint32_t pa[4];
            pa[0] = f2tf(odd ? q01 : q00);   // P(r0, kk*8 + t)
            pa[1] = f2tf(odd ? q11 : q10);   // P(r1, kk*8 + t)
            pa[2] = f2tf(odd ? q21 : q20);   // P(r0, kk*8 + t + 4)
            pa[3] = f2tf(odd ? q31 : q30);   // P(r1, kk*8 + t + 4)
#pragma unroll
            for (int ntp = 0; ntp < 4; ++ntp) {
                uint32_t v0, v1, v2, v3;
                ldsm4(v0, v1, v2, v3, tladdr + ntp * (PT * 64) + kk * 32);
                uint32_t b0[2] = { v0, v1 };
                mma_tf32(oacc[2 * ntp], pa, b0);
                uint32_t b1[2] = { v2, v3 };
                mma_tf32(oacc[2 * ntp + 1], pa, b1);
            }
        }
    }
}

__global__ void __launch_bounds__(NTH, 2)
omni_attn_mma(const float* __restrict__ q,
              const float* __restrict__ k,
              const float* __restrict__ v,
              const int* __restrict__ pad_ends,
              const int* __restrict__ full_starts,
              const int* __restrict__ full_ends,
              const int* __restrict__ p_bt2i,
              const int* __restrict__ p_blm,
              float* __restrict__ out)
{
    extern __shared__ uint32_t sm[];
    const uint32_t sb = smem_u32(sm);

    const int tid  = threadIdx.x;
    const int wid  = tid >> 5;        // 0..7
    const int lane = tid & 31;
    const int g    = lane >> 2;       // 0..7
    const int t    = lane & 3;        // 0..3
    const int m0   = wid * 16;        // warp's q-row base within tile
    const int head = blockIdx.y;
    const int b    = head / HH;
    const int q0   = blockIdx.x * BM;

    const int bt2i = p_bt2i[0];
    const int blm  = p_blm[0];
    const int cat  = (b < bt2i) ? 0 : ((b < bt2i + blm) ? 1 : 2);

    // per-lane ldmatrix base addresses
    const int lrow  = lane & 7;
    const int halfb = (lane >> 3) & 1;
    const int pairi = lane >> 4;
    const uint32_t qladdr = sb + 4u * ((uint32_t)(m0 + (lane & 15)) * PQ + (lane >> 4) * 4);
    const uint32_t kladdr = sb + 4u * (O_K + (uint32_t)(pairi * 8 + lrow) * PQ + halfb * 4);
    const uint32_t tladdr = sb + 4u * (O_T + (uint32_t)(pairi * 8 + lrow) * PT + halfb * 4);

    // ---- stage Q once: scaled to log2 domain, tf32 bits, pitch PQ ----
    {
        const float sc = 0.125f * LOG2E;
        const float4* qg = reinterpret_cast<const float4*>(q + ((size_t)head * SQ + q0) * DD);
#pragma unroll
        for (int it = 0; it < 8; ++it) {
            int idx = tid + it * NTH;          // 0..2047
            int row = idx >> 4, c4 = idx & 15;
            float4 tq = qg[idx];
            uint4 u = { f2tf(tq.x * sc), f2tf(tq.y * sc), f2tf(tq.z * sc), f2tf(tq.w * sc) };
            *reinterpret_cast<uint4*>(&sm[O_Q + row * PQ + c4 * 4]) = u;
        }
    }

    int fs2[2] = {0, 0}, fe2[2] = {0, 0};
    if (cat == 0) {
#pragma unroll
        for (int h = 0; h < 2; ++h) {
            int r = q0 + m0 + g + h * 8;
            fs2[h] = full_starts[r];
            fe2[h] = full_ends[r];
        }
    }

    float oacc[8][4];
#pragma unroll
    for (int nt = 0; nt < 8; ++nt)
#pragma unroll
        for (int u = 0; u < 4; ++u) oacc[nt][u] = 0.0f;
    float lacc[2] = {0.0f, 0.0f};

    int ntc_full;
    if (cat == 0)      ntc_full = SQ / BN;
    else if (cat == 1) ntc_full = (q0 + BM) / BN;
    else {
        int ntc = (q0 + BM) / BN;
        int ntm = NCLIP3 / BN + 1;
        ntc_full = (ntc > ntm) ? ntc : ntm;
        if (ntc_full > SQ / BN) ntc_full = SQ / BN;
    }

    const float* kbase  = k + (size_t)head * SQ * DD;
    const float* vbase  = v + (size_t)head * SQ * DD;
    const int*   padrow = pad_ends + b * SQ;

    if (cat == 0)
        attn_loop<0>(sm, qladdr, kladdr, tladdr, kbase, vbase, padrow, ntc_full,
                     q0, tid, m0, g, t, fs2, fe2, oacc, lacc);
    else if (cat == 1)
        attn_loop<1>(sm, qladdr, kladdr, tladdr, kbase, vbase, padrow, ntc_full,
                     q0, tid, m0, g, t, fs2, fe2, oacc, lacc);
    else
        attn_loop<2>(sm, qladdr, kladdr, tladdr, kbase, vbase, padrow, ntc_full,
                     q0, tid, m0, g, t, fs2, fe2, oacc, lacc);

    // ---- epilogue: normalize fragments and store ----
#pragma unroll
    for (int h = 0; h < 2; ++h) {
        const float inv = 1.0f / lacc[h];
        const int r = q0 + m0 + g + h * 8;
        float* op = out + ((size_t)head * SQ + r) * DD;
#pragma unroll
        for (int nt = 0; nt < 8; ++nt) {
            float2 o;
            o.x = oacc[nt][h * 2 + 0] * inv;
            o.y = oacc[nt][h * 2 + 1] * inv;
            *reinterpret_cast<float2*>(op + nt * 8 + 2 * t) = o;
        }
    }
}

extern "C" void kernel_launch(void* const* d_in, const int* in_sizes, int n_in,
                              void* d_out, int out_size) {
    const float* q  = (const float*)d_in[0];
    const float* k  = (const float*)d_in[1];
    const float* v  = (const float*)d_in[2];
    const int* pad_ends    = (const int*)d_in[3];
    const int* full_starts = (const int*)d_in[4];
    const int* full_ends   = (const int*)d_in[5];
    const int* bt2i        = (const int*)d_in[6];
    const int* blm         = (const int*)d_in[7];
    float* out = (float*)d_out;

    static int configured = 0;
    if (!configured) {
        cudaFuncSetAttribute(omni_attn_mma,
                             cudaFuncAttributeMaxDynamicSharedMemorySize, SMEM_BYTES);
        configured = 1;
    }

    dim3 grid(SQ / BM, 12 * HH);
    dim3 block(NTH);
    omni_attn_mma<<<grid, block, SMEM_BYTES>>>(q, k, v, pad_ends, full_starts, full_ends,
                                               bt2i, blm, out);
}

// round 17
// speedup vs baseline: 4.2612x; 1.1623x over previous
#include <cuda_runtime.h>
#include <cstdint>

#define SQ 1024
#define DD 64
#define HH 8
#define BM 128
#define BN 64
#define NTH 128         // 4 warps, M=32 per warp
#define PQ 68           // pitch (words) for Q and K tiles (68 % 32 == 4)
#define PT 68           // pitch (words) for Vt tile
#define NCLIP3 579
#define MASKED_L2 (-72.0f)
#define LOG2E 1.4426950408889634f

// smem layout in 32-bit words
#define O_Q   0                    // 128 x 68
#define O_K   (BM * PQ)            // 64 x 68
#define O_T   (O_K + BN * PQ)      // Vt: 64 x 68
#define O_PAD (O_T + DD * PT)      // 64 ints
#define SMEM_WORDS (O_PAD + BN)
#define SMEM_BYTES (SMEM_WORDS * 4)

static __device__ __forceinline__ uint32_t f2tf(float x) {
    uint32_t r;
    asm("cvt.rna.tf32.f32 %0, %1;" : "=r"(r) : "f"(x));
    return r;
}
static __device__ __forceinline__ float ex2f(float x) {
    float r;
    asm("ex2.approx.f32 %0, %1;" : "=f"(r) : "f"(x));
    return r;
}
static __device__ __forceinline__ void mma_tf32(float* c, const uint32_t* a,
                                                const uint32_t* b) {
    asm volatile(
        "mma.sync.aligned.m16n8k8.row.col.f32.tf32.tf32.f32 "
        "{%0,%1,%2,%3}, {%4,%5,%6,%7}, {%8,%9}, {%0,%1,%2,%3};"
        : "+f"(c[0]), "+f"(c[1]), "+f"(c[2]), "+f"(c[3])
        : "r"(a[0]), "r"(a[1]), "r"(a[2]), "r"(a[3]), "r"(b[0]), "r"(b[1]));
}
static __device__ __forceinline__ void ldsm4(uint32_t& r0, uint32_t& r1,
                                             uint32_t& r2, uint32_t& r3,
                                             uint32_t addr) {
    asm volatile("ldmatrix.sync.aligned.m8n8.x4.shared.b16 {%0,%1,%2,%3}, [%4];"
                 : "=r"(r0), "=r"(r1), "=r"(r2), "=r"(r3) : "r"(addr));
}
static __device__ __forceinline__ uint32_t smem_u32(const void* p) {
    uint32_t a;
    asm("{ .reg .u64 t; cvta.to.shared.u64 t, %1; cvt.u32.u64 %0, t; }" : "=r"(a) : "l"(p));
    return a;
}

// CAT 0 (t2i): eye ^ ((!pad && causal) || full)
// CAT 1 (lm):  causal ; CAT 2 (mmu): causal || kv<=579
template <int CAT>
static __device__ __forceinline__ bool mask_fn(int r, int kv, int pad_end,
                                               int fs, int fe) {
    if (CAT == 1) return r >= kv;
    if (CAT == 2) return (r >= kv) || (kv <= NCLIP3);
    bool pad    = kv < pad_end;
    bool causal = (!pad) && (r >= kv);
    bool full   = (kv >= fs) && (kv < fe);
    return ((r == kv) ? 1 : 0) ^ ((causal || full) ? 1 : 0);
}

template <int CAT>
static __device__ __forceinline__ void attn_loop(
    uint32_t* __restrict__ sm,
    uint32_t qladdr, uint32_t kladdr, uint32_t tladdr,
    const float* kbase, const float* vbase, const int* padrow,
    int nt_count, int q0, int tid, int m0, int g, int t,
    const int (&fs4)[4], const int (&fe4)[4],
    float (&oacc)[2][8][4], float (&lacc)[4])
{
    uint32_t* Ks = sm + O_K;
    uint32_t* Ts = sm + O_T;
    int*      pads = (int*)(sm + O_PAD);

    const int lane = tid & 31;
    const int src0 = (lane & 28) | (t >> 1);
    const int src2 = src0 + 2;
    const bool odd = (t & 1) != 0;

    // V column-staging mapping
    const int vd   = tid & 63;        // d index (0..63)
    const int vgs  = tid >> 6;        // 0..1

    for (int tt = 0; tt < nt_count; ++tt) {
        const int kv0 = tt * BN;
        __syncthreads();   // previous GEMM2 finished reading Ks/Ts

        // ---- stage K (row-major, pitch PQ), tf32 ----
        {
            const float4* kg = reinterpret_cast<const float4*>(kbase + (size_t)kv0 * DD);
#pragma unroll
            for (int it = 0; it < 8; ++it) {
                int idx = tid + it * NTH;          // 0..1023
                int row = idx >> 4, c4 = idx & 15;
                float4 kvl = kg[idx];
                uint4 ku = { f2tf(kvl.x), f2tf(kvl.y), f2tf(kvl.z), f2tf(kvl.w) };
                *reinterpret_cast<uint4*>(&Ks[row * PQ + c4 * 4]) = ku;
            }
        }
        // ---- stage V transposed, conflict-free: column reads, float4 row writes ----
        {
#pragma unroll
            for (int it = 0; it < 8; ++it) {
                int kvg = vgs + it * 2;            // granule 0..15
                const float* vcol = vbase + (size_t)(kv0 + 4 * kvg) * DD + vd;
                uint4 w;
                w.x = f2tf(vcol[0]);
                w.y = f2tf(vcol[DD]);
                w.z = f2tf(vcol[2 * DD]);
                w.w = f2tf(vcol[3 * DD]);
                *reinterpret_cast<uint4*>(&Ts[vd * PT + 4 * kvg]) = w;
            }
        }
        if (CAT == 0 && tid < BN) pads[tid] = padrow[kv0 + tid];
        __syncthreads();

        // ---- GEMM1: S = Q K^T  (M=32 per warp) ----
        float sacc[2][8][4];
#pragma unroll
        for (int mh = 0; mh < 2; ++mh)
#pragma unroll
            for (int nt = 0; nt < 8; ++nt)
#pragma unroll
                for (int u = 0; u < 4; ++u) sacc[mh][nt][u] = 0.0f;

#pragma unroll
        for (int kk = 0; kk < 8; ++kk) {
            uint32_t a0[4], a1[4];
            ldsm4(a0[0], a0[1], a0[2], a0[3], qladdr + kk * 32);
            ldsm4(a1[0], a1[1], a1[2], a1[3], qladdr + 16 * PQ * 4 + kk * 32);
#pragma unroll
            for (int ntp = 0; ntp < 4; ++ntp) {
                uint32_t k0, k1, k2, k3;
                ldsm4(k0, k1, k2, k3, kladdr + ntp * (PQ * 64) + kk * 32);
                uint32_t b0[2] = { k0, k1 };
                uint32_t b1[2] = { k2, k3 };
                mma_tf32(sacc[0][2 * ntp],     a0, b0);
                mma_tf32(sacc[0][2 * ntp + 1], a0, b1);
                mma_tf32(sacc[1][2 * ntp],     a1, b0);
                mma_tf32(sacc[1][2 * ntp + 1], a1, b1);
            }
        }

        // ---- epilogue: mask + exp2 + rowsum (P stays in regs) ----
#pragma unroll
        for (int mh = 0; mh < 2; ++mh) {
            float rs0 = 0.0f, rs1 = 0.0f;
            const int r0 = q0 + m0 + mh * 16 + g;
            const int r1 = r0 + 8;
#pragma unroll
            for (int nt = 0; nt < 8; ++nt) {
                const int kvA = kv0 + nt * 8 + 2 * t;
                const int kvB = kvA + 1;
                int peA = 0, peB = 0;
                if (CAT == 0) {
                    int2 pe2 = *reinterpret_cast<const int2*>(&pads[nt * 8 + 2 * t]);
                    peA = pe2.x; peB = pe2.y;
                }
                float s0 = mask_fn<CAT>(r0, kvA, peA, fs4[mh * 2 + 0], fe4[mh * 2 + 0]) ? sacc[mh][nt][0] : MASKED_L2;
                float s1 = mask_fn<CAT>(r0, kvB, peB, fs4[mh * 2 + 0], fe4[mh * 2 + 0]) ? sacc[mh][nt][1] : MASKED_L2;
                float s2 = mask_fn<CAT>(r1, kvA, peA, fs4[mh * 2 + 1], fe4[mh * 2 + 1]) ? sacc[mh][nt][2] : MASKED_L2;
                float s3 = mask_fn<CAT>(r1, kvB, peB, fs4[mh * 2 + 1], fe4[mh * 2 + 1]) ? sacc[mh][nt][3] : MASKED_L2;
                float p0 = ex2f(s0), p1 = ex2f(s1), p2 = ex2f(s2), p3 = ex2f(s3);
                rs0 += p0 + p1;
                rs1 += p2 + p3;
                sacc[mh][nt][0] = p0; sacc[mh][nt][1] = p1;
                sacc[mh][nt][2] = p2; sacc[mh][nt][3] = p3;
            }
            rs0 += __shfl_xor_sync(0xffffffffu, rs0, 1);
            rs0 += __shfl_xor_sync(0xffffffffu, rs0, 2);
            rs1 += __shfl_xor_sync(0xffffffffu, rs1, 1);
            rs1 += __shfl_xor_sync(0xffffffffu, rs1, 2);
            lacc[mh * 2 + 0] += rs0;
            lacc[mh * 2 + 1] += rs1;
        }

        // ---- GEMM2: O += P V  (A-frags built via quad shuffles) ----
#pragma unroll
        for (int kk = 0; kk < 8; ++kk) {
            uint32_t pa[2][4];
#pragma unroll
            for (int mh = 0; mh < 2; ++mh) {
                float q00 = __shfl_sync(0xffffffffu, sacc[mh][kk][0], src0);
                float q01 = __shfl_sync(0xffffffffu, sacc[mh][kk][1], src0);
                float q10 = __shfl_sync(0xffffffffu, sacc[mh][kk][2], src0);
                float q11 = __shfl_sync(0xffffffffu, sacc[mh][kk][3], src0);
                float q20 = __shfl_sync(0xffffffffu, sacc[mh][kk][0], src2);
                float q21 = __shfl_sync(0xffffffffu, sacc[mh][kk][1], src2);
                float q30 = __shfl_sync(0xffffffffu, sacc[mh][kk][2], src2);
                float q31 = __shfl_sync(0xffffffffu, sacc[mh][kk][3], src2);
                pa[mh][0] = f2tf(odd ? q01 : q00);   // P(r0, kk*8 + t)
                pa[mh][1] = f2tf(odd ? q11 : q10);   // P(r1, kk*8 + t)
                pa[mh][2] = f2tf(odd ? q21 : q20);   // P(r0, kk*8 + t + 4)
                pa[mh][3] = f2tf(odd ? q31 : q30);   // P(r1, kk*8 + t + 4)
            }
#pragma unroll
            for (int ntp = 0; ntp < 4; ++ntp) {
                uint32_t v0, v1, v2, v3;
                ldsm4(v0, v1, v2, v3, tladdr + ntp * (PT * 64) + kk * 32);
                uint32_t b0[2] = { v0, v1 };
                uint32_t b1[2] = { v2, v3 };
                mma_tf32(oacc[0][2 * ntp],     pa[0], b0);
                mma_tf32(oacc[0][2 * ntp + 1], pa[0], b1);
                mma_tf32(oacc[1][2 * ntp],     pa[1], b0);
                mma_tf32(oacc[1][2 * ntp + 1], pa[1], b1);
            }
        }
    }
}

__global__ void __launch_bounds__(NTH, 2)
omni_attn_mma(const float* __restrict__ q,
              const float* __restrict__ k,
              const float* __restrict__ v,
              const int* __restrict__ pad_ends,
              const int* __restrict__ full_starts,
              const int* __restrict__ full_ends,
              const int* __restrict__ p_bt2i,
              const int* __restrict__ p_blm,
              float* __restrict__ out)
{
    extern __shared__ uint32_t sm[];
    const uint32_t sb = smem_u32(sm);

    const int tid  = threadIdx.x;
    const int wid  = tid >> 5;        // 0..3
    const int lane = tid & 31;
    const int g    = lane >> 2;       // 0..7
    const int t    = lane & 3;        // 0..3
    const int m0   = wid * 32;        // warp's q-row base within tile
    const int head = blockIdx.y;
    const int b    = head / HH;
    const int q0   = blockIdx.x * BM;

    const int bt2i = p_bt2i[0];
    const int blm  = p_blm[0];
    const int cat  = (b < bt2i) ? 0 : ((b < bt2i + blm) ? 1 : 2);

    // per-lane ldmatrix base addresses
    const int lrow  = lane & 7;
    const int halfb = (lane >> 3) & 1;
    const int pairi = lane >> 4;
    const uint32_t qladdr = sb + 4u * ((uint32_t)(m0 + (lane & 15)) * PQ + (lane >> 4) * 4);
    const uint32_t kladdr = sb + 4u * (O_K + (uint32_t)(pairi * 8 + lrow) * PQ + halfb * 4);
    const uint32_t tladdr = sb + 4u * (O_T + (uint32_t)(pairi * 8 + lrow) * PT + halfb * 4);

    // ---- stage Q once: scaled to log2 domain, tf32 bits, pitch PQ ----
    {
        const float sc = 0.125f * LOG2E;
        const float4* qg = reinterpret_cast<const float4*>(q + ((size_t)head * SQ + q0) * DD);
#pragma unroll
        for (int it = 0; it < 16; ++it) {
            int idx = tid + it * NTH;          // 0..2047
            int row = idx >> 4, c4 = idx & 15;
            float4 tq = qg[idx];
            uint4 u = { f2tf(tq.x * sc), f2tf(tq.y * sc), f2tf(tq.z * sc), f2tf(tq.w * sc) };
            *reinterpret_cast<uint4*>(&sm[O_Q + row * PQ + c4 * 4]) = u;
        }
    }

    int fs4[4] = {0, 0, 0, 0}, fe4[4] = {0, 0, 0, 0};
    if (cat == 0) {
#pragma unroll
        for (int mh = 0; mh < 2; ++mh)
#pragma unroll
            for (int h = 0; h < 2; ++h) {
                int r = q0 + m0 + mh * 16 + g + h * 8;
                fs4[mh * 2 + h] = full_starts[r];
                fe4[mh * 2 + h] = full_ends[r];
            }
    }

    float oacc[2][8][4];
#pragma unroll
    for (int mh = 0; mh < 2; ++mh)
#pragma unroll
        for (int nt = 0; nt < 8; ++nt)
#pragma unroll
            for (int u = 0; u < 4; ++u) oacc[mh][nt][u] = 0.0f;
    float lacc[4] = {0.0f, 0.0f, 0.0f, 0.0f};

    int ntc_full;
    if (cat == 0)      ntc_full = SQ / BN;
    else if (cat == 1) ntc_full = (q0 + BM) / BN;
    else {
        int ntc = (q0 + BM) / BN;
        int ntm = NCLIP3 / BN + 1;
        ntc_full = (ntc > ntm) ? ntc : ntm;
        if (ntc_full > SQ / BN) ntc_full = SQ / BN;
    }

    const float* kbase  = k + (size_t)head * SQ * DD;
    const float* vbase  = v + (size_t)head * SQ * DD;
    const int*   padrow = pad_ends + b * SQ;

    if (cat == 0)
        attn_loop<0>(sm, qladdr, kladdr, tladdr, kbase, vbase, padrow, ntc_full,
                     q0, tid, m0, g, t, fs4, fe4, oacc, lacc);
    else if (cat == 1)
        attn_loop<1>(sm, qladdr, kladdr, tladdr, kbase, vbase, padrow, ntc_full,
                     q0, tid, m0, g, t, fs4, fe4, oacc, lacc);
    else
        attn_loop<2>(sm, qladdr, kladdr, tladdr, kbase, vbase, padrow, ntc_full,
                     q0, tid, m0, g, t, fs4, fe4, oacc, lacc);

    // ---- epilogue: normalize fragments and store ----
#pragma unroll
    for (int mh = 0; mh < 2; ++mh)
#pragma unroll
        for (int h = 0; h < 2; ++h) {
            const float inv = 1.0f / lacc[mh * 2 + h];
            const int r = q0 + m0 + mh * 16 + g + h * 8;
            float* op = out + ((size_t)head * SQ + r) * DD;
#pragma unroll
            for (int nt = 0; nt < 8; ++nt) {
                float2 o;
                o.x = oacc[mh][nt][h * 2 + 0] * inv;
                o.y = oacc[mh][nt][h * 2 + 1] * inv;
                *reinterpret_cast<float2*>(op + nt * 8 + 2 * t) = o;
            }
        }
}

extern "C" void kernel_launch(void* const* d_in, const int* in_sizes, int n_in,
                              void* d_out, int out_size) {
    const float* q  = (const float*)d_in[0];
    const float* k  = (const float*)d_in[1];
    const float* v  = (const float*)d_in[2];
    const int* pad_ends    = (const int*)d_in[3];
    const int* full_starts = (const int*)d_in[4];
    const int* full_ends   = (const int*)d_in[5];
    const int* bt2i        = (const int*)d_in[6];
    const int* blm         = (const int*)d_in[7];
    float* out = (float*)d_out;

    static int configured = 0;
    if (!configured) {
        cudaFuncSetAttribute(omni_attn_mma,
                             cudaFuncAttributeMaxDynamicSharedMemorySize, SMEM_BYTES);
        configured = 1;
    }

    dim3 grid(SQ / BM, 12 * HH);
    dim3 block(NTH);
    omni_attn_mma<<<grid, block, SMEM_BYTES>>>(q, k, v, pad_ends, full_starts, full_ends,
                                               bt2i, blm, out);
}